// round 13
// baseline (speedup 1.0000x reference)
#include <cuda_runtime.h>
#include <cuda_bf16.h>
#include <cuda_fp16.h>
#include <cstdint>

#define NN 100000
#define EE 600000
#define RR 3
#define DIN 256
#define DH  128
#define NCLS 16
#define NEG_SLOPE 0.01f

#define SCAN_N (RR * NN)
#define SCAN_B 1024
#define SCAN_NB ((SCAN_N + SCAN_B - 1) / SCAN_B)

// GEMM tiling: KC=64, 2 smem tiles per stage (A, B), double buffered
#define KC 64
#define ASTR 72
#define TILE_B (128 * ASTR * 2)     // 18432 B
#define STAGE_B (2 * TILE_B)        // 36864 B
#define GS_TOTAL (2 * STAGE_B)      // 73728 B

__device__ __forceinline__ uint32_t smem_u32(const void* p) {
    uint32_t a;
    asm("{ .reg .u64 t; cvta.to.shared.u64 t, %1; cvt.u32.u64 %0, t; }" : "=r"(a) : "l"(p));
    return a;
}

#define LDSM4(r, a) \
    asm volatile("ldmatrix.sync.aligned.m8n8.x4.shared.b16 {%0,%1,%2,%3}, [%4];" \
        : "=r"((r)[0]), "=r"((r)[1]), "=r"((r)[2]), "=r"((r)[3]) : "r"(a))

__device__ __forceinline__ void mma16816h(float* d, const uint32_t* a, const uint32_t* b) {
    asm volatile("mma.sync.aligned.m16n8k16.row.col.f32.f16.f16.f32 "
                 "{%0,%1,%2,%3}, {%4,%5,%6,%7}, {%8,%9}, {%0,%1,%2,%3};"
                 : "+f"(d[0]), "+f"(d[1]), "+f"(d[2]), "+f"(d[3])
                 : "r"(a[0]), "r"(a[1]), "r"(a[2]), "r"(a[3]), "r"(b[0]), "r"(b[1]));
}

// ================= scratch =================
__device__ __half g_z[(size_t)RR * NN * DH];          // fp16 z: 77 MB (fits L2)
__device__ __half g_x16[(size_t)NN * DIN];
__device__ __half g_h16[(size_t)NN * DH];
__device__ __half g_w0[RR * DH * DIN];                // transposed [r][n][k], fp16
__device__ __half g_w1[RR * DH * DH];
__device__ float g_so[SCAN_N];
__device__ float g_si[SCAN_N];
__device__ int   g_co[SCAN_N];
__device__ int   g_ci[SCAN_N];
__device__ int   g_off[SCAN_N + 1];
__device__ int   g_cursor[SCAN_N];
__device__ int   g_bsum[SCAN_NB];
__device__ int2  g_edge[RR * EE];     // {src, float_bits(so[src]*si[dst])}

// ================= degrees + CSR =================
__global__ void deg_zero_kernel() {
    int i = blockIdx.x * blockDim.x + threadIdx.x;
    if (i < SCAN_N) { g_co[i] = 0; g_ci[i] = 0; }
}
__global__ void deg_hist_kernel(const int* __restrict__ src, const int* __restrict__ dst) {
    int i = blockIdx.x * blockDim.x + threadIdx.x;
    if (i >= RR * EE) return;
    int r = i / EE;
    atomicAdd(&g_co[r * NN + src[i]], 1);
    atomicAdd(&g_ci[r * NN + dst[i]], 1);
}
__global__ void deg_scale_kernel() {
    int i = blockIdx.x * blockDim.x + threadIdx.x;
    if (i >= SCAN_N) return;
    int co = g_co[i]; if (co < 1) co = 1;
    int ci = g_ci[i]; if (ci < 1) ci = 1;
    g_so[i] = rsqrtf((float)co);
    g_si[i] = rsqrtf((float)ci);
}
__global__ void scan1_kernel() {
    __shared__ int tmp[SCAN_B];
    int t = threadIdx.x;
    int i = blockIdx.x * SCAN_B + t;
    int v = (i < SCAN_N) ? g_ci[i] : 0;
    tmp[t] = v;
    __syncthreads();
    for (int o = 1; o < SCAN_B; o <<= 1) {
        int u = (t >= o) ? tmp[t - o] : 0;
        __syncthreads();
        tmp[t] += u;
        __syncthreads();
    }
    if (i < SCAN_N) g_off[i] = tmp[t] - v;
    if (t == SCAN_B - 1) g_bsum[blockIdx.x] = tmp[t];
}
__global__ void scan2_kernel() {
    if (threadIdx.x == 0 && blockIdx.x == 0) {
        int run = 0;
        for (int b = 0; b < SCAN_NB; b++) { int v = g_bsum[b]; g_bsum[b] = run; run += v; }
        g_off[SCAN_N] = run;
    }
}
__global__ void scan3_kernel() {
    int i = blockIdx.x * SCAN_B + threadIdx.x;
    if (i < SCAN_N) {
        int v = g_off[i] + g_bsum[blockIdx.x];
        g_off[i] = v;
        g_cursor[i] = v;
    }
}
__global__ void fill_kernel(const int* __restrict__ src, const int* __restrict__ dst) {
    int i = blockIdx.x * blockDim.x + threadIdx.x;
    if (i >= RR * EE) return;
    int r = i / EE;
    int s = src[i], d = dst[i];
    int pos = atomicAdd(&g_cursor[r * NN + d], 1);
    float coef = g_so[r * NN + s] * g_si[r * NN + d];
    g_edge[pos] = make_int2(s, __float_as_int(coef));
}

// ================= fp16 conversions =================
__global__ void conv_x_kernel(const float* __restrict__ in,
                              __half* __restrict__ o16, size_t n4) {
    size_t i = (size_t)blockIdx.x * blockDim.x + threadIdx.x;
    if (i >= n4) return;
    float4 v = ((const float4*)in)[i];
    __half2 h0 = __floats2half2_rn(v.x, v.y);
    __half2 h1 = __floats2half2_rn(v.z, v.w);
    ((__half2*)o16)[i * 2]     = h0;
    ((__half2*)o16)[i * 2 + 1] = h1;
}

// W [RR, K, DH] -> Wt fp16 [RR, DH(n), K]
__global__ void wconv_kernel(const float* __restrict__ W,
                             __half* __restrict__ t, int K) {
    int i = blockIdx.x * blockDim.x + threadIdx.x;
    if (i >= RR * K * DH) return;
    int r = i / (K * DH);
    int rem = i - r * K * DH;
    int k = rem / DH;
    int n = rem - k * DH;
    t[(size_t)r * DH * K + (size_t)n * K + k] = __float2half_rn(W[i]);
}

// ================= plain fp16 GEMM (KC=64, 2 CTAs/SM) =================
__device__ __forceinline__ void load_stage(uint32_t sb, int st, int c, int K, int mbase,
                                           const __half* __restrict__ A,
                                           const __half* __restrict__ B, int tid) {
    int k0 = c * KC;
    uint32_t sbase = sb + st * STAGE_B;
#pragma unroll
    for (int i = 0; i < 8; i++) {
        int idx = tid + i * 256;          // 2048 = 2 tiles x 1024 segs
        int tile = idx >> 10;
        int p = idx & 1023;
        int row = p >> 3, seg = p & 7;    // 8 segs of 16B per 128B row
        uint32_t sa = sbase + tile * TILE_B + row * (ASTR * 2) + seg * 16;
        const __half* gsrc;
        int sz = 16;
        if (tile == 0) {
            int grow = mbase + row;
            gsrc = A + (size_t)grow * K + k0 + seg * 8;
            if (grow >= NN) sz = 0;
        } else {
            gsrc = B + (size_t)row * K + k0 + seg * 8;
        }
        asm volatile("cp.async.cg.shared.global [%0], [%1], 16, %2;"
                     :: "r"(sa), "l"(gsrc), "r"(sz));
    }
    asm volatile("cp.async.commit_group;" ::: "memory");
}

__global__ __launch_bounds__(256, 2)
void mma_gemm(int K,
              const __half* __restrict__ A,
              const __half* __restrict__ Ball,
              __half* __restrict__ Call) {
    extern __shared__ char smem[];
    uint32_t sb = smem_u32(smem);
    int tid = threadIdx.x, wid = tid >> 5, lane = tid & 31;
    int r = blockIdx.x;                  // fast dim: relation (A shared in L2)
    int mbase = blockIdx.y * 128;
    const __half* B = Ball + (size_t)r * DH * K;
    __half* C = Call + (size_t)r * NN * DH;
    const int warp_m = (wid & 3) * 32;
    const int warp_n = (wid >> 2) * 64;

    float acc[2][8][4];
#pragma unroll
    for (int mt = 0; mt < 2; mt++)
#pragma unroll
        for (int nt = 0; nt < 8; nt++)
#pragma unroll
            for (int q = 0; q < 4; q++) acc[mt][nt][q] = 0.0f;

    const int nchunk = K / KC;
    load_stage(sb, 0, 0, K, mbase, A, B, tid);

    for (int c = 0; c < nchunk; c++) {
        if (c + 1 < nchunk) {
            load_stage(sb, (c + 1) & 1, c + 1, K, mbase, A, B, tid);
            asm volatile("cp.async.wait_group 1;" ::: "memory");
        } else {
            asm volatile("cp.async.wait_group 0;" ::: "memory");
        }
        __syncthreads();

        uint32_t base = sb + (c & 1) * STAGE_B;
#pragma unroll
        for (int ks = 0; ks < KC; ks += 16) {
            uint32_t ah[2][4];
            const int ar = lane & 15;
            const int ac = ks + ((lane >> 4) << 3);
#pragma unroll
            for (int mt = 0; mt < 2; mt++) {
                uint32_t addr = base + ((warp_m + mt * 16 + ar) * ASTR + ac) * 2;
                LDSM4(ah[mt], addr);
            }
            const int br = ((lane >> 4) << 3) + (lane & 7);
            const int bc = ks + (((lane >> 3) & 1) << 3);
#pragma unroll
            for (int j = 0; j < 4; j++) {
                uint32_t b4[4];
                uint32_t addr = base + TILE_B + ((warp_n + j * 16 + br) * ASTR + bc) * 2;
                LDSM4(b4, addr);
#pragma unroll
                for (int mt = 0; mt < 2; mt++) {
#pragma unroll
                    for (int half = 0; half < 2; half++) {
                        mma16816h(acc[mt][j * 2 + half], ah[mt], &b4[half * 2]);
                    }
                }
            }
        }
        __syncthreads();
    }

    // epilogue: fp32 acc -> fp16 z
#pragma unroll
    for (int mt = 0; mt < 2; mt++) {
        int row0 = mbase + warp_m + mt * 16 + (lane >> 2);
#pragma unroll
        for (int nt = 0; nt < 8; nt++) {
            int col = warp_n + nt * 8 + (lane & 3) * 2;
            if (row0 < NN)
                *(__half2*)(C + (size_t)row0 * DH + col) =
                    __floats2half2_rn(acc[mt][nt][0], acc[mt][nt][1]);
            if (row0 + 8 < NN)
                *(__half2*)(C + (size_t)(row0 + 8) * DH + col) =
                    __floats2half2_rn(acc[mt][nt][2], acc[mt][nt][3]);
        }
    }
}

// ================= gather: warp per dst node, int4 edge pairs + prefetch =================
// MODE 0: leaky -> h fp16.  MODE 1: h2 f32 out + fused logits.
template <int MODE>
__global__ __launch_bounds__(256)
void gather_kernel(const __half* __restrict__ z, const float* __restrict__ bias,
                   float* __restrict__ outf, __half* __restrict__ outh,
                   const float* __restrict__ fcW, const float* __restrict__ fcb,
                   float* __restrict__ logits) {
    int lane = threadIdx.x & 31;
    int c0 = lane * 4;
    int w = blockIdx.x * 8 + (threadIdx.x >> 5);   // NN % 8 == 0: always valid

    if (MODE == 1) {
        __shared__ float WsL[DH * NCLS];
        __shared__ float bsL[NCLS];
        for (int i = threadIdx.x; i < DH * NCLS; i += 256) WsL[i] = fcW[i];
        if (threadIdx.x < NCLS) bsL[threadIdx.x] = fcb[threadIdx.x];
        __syncthreads();

        // fall through handled below via pointers
        float accT[4];
#pragma unroll
        for (int j = 0; j < 4; j++)
            accT[j] = bias[c0 + j] + bias[DH + c0 + j] + bias[2 * DH + c0 + j];

#pragma unroll
        for (int r = 0; r < RR; r++) {
            int idx = r * NN + w;
            int e = g_off[idx];
            int end = g_off[idx + 1];
            const __half* zr = z + (size_t)r * NN * DH;
            if ((e & 1) && e < end) {
                int2 ed = __ldg(&g_edge[e]);
                uint2 u = __ldg((const uint2*)(zr + (size_t)ed.x * DH + c0));
                float cf = __int_as_float(ed.y);
                float2 p0 = __half22float2(*(__half2*)&u.x);
                float2 p1 = __half22float2(*(__half2*)&u.y);
                accT[0] = fmaf(cf, p0.x, accT[0]);
                accT[1] = fmaf(cf, p0.y, accT[1]);
                accT[2] = fmaf(cf, p1.x, accT[2]);
                accT[3] = fmaf(cf, p1.y, accT[3]);
                e++;
            }
            int npair = (end - e) >> 1;
            if (npair > 0) {
                int4 ed = __ldg((const int4*)(g_edge + e));
                for (int it = 1; it < npair; it++) {
                    uint2 u0 = __ldg((const uint2*)(zr + (size_t)ed.x * DH + c0));
                    uint2 u1 = __ldg((const uint2*)(zr + (size_t)ed.z * DH + c0));
                    int4 nx = __ldg((const int4*)(g_edge + e + 2));
                    float cf0 = __int_as_float(ed.y);
                    float cf1 = __int_as_float(ed.w);
                    float2 a0 = __half22float2(*(__half2*)&u0.x);
                    float2 b0 = __half22float2(*(__half2*)&u0.y);
                    float2 a1 = __half22float2(*(__half2*)&u1.x);
                    float2 b1 = __half22float2(*(__half2*)&u1.y);
                    accT[0] = fmaf(cf0, a0.x, accT[0]);
                    accT[1] = fmaf(cf0, a0.y, accT[1]);
                    accT[2] = fmaf(cf0, b0.x, accT[2]);
                    accT[3] = fmaf(cf0, b0.y, accT[3]);
                    accT[0] = fmaf(cf1, a1.x, accT[0]);
                    accT[1] = fmaf(cf1, a1.y, accT[1]);
                    accT[2] = fmaf(cf1, b1.x, accT[2]);
                    accT[3] = fmaf(cf1, b1.y, accT[3]);
                    ed = nx;
                    e += 2;
                }
                uint2 u0 = __ldg((const uint2*)(zr + (size_t)ed.x * DH + c0));
                uint2 u1 = __ldg((const uint2*)(zr + (size_t)ed.z * DH + c0));
                float cf0 = __int_as_float(ed.y);
                float cf1 = __int_as_float(ed.w);
                float2 a0 = __half22float2(*(__half2*)&u0.x);
                float2 b0 = __half22float2(*(__half2*)&u0.y);
                float2 a1 = __half22float2(*(__half2*)&u1.x);
                float2 b1 = __half22float2(*(__half2*)&u1.y);
                accT[0] = fmaf(cf0, a0.x, accT[0]);
                accT[1] = fmaf(cf0, a0.y, accT[1]);
                accT[2] = fmaf(cf0, b0.x, accT[2]);
                accT[3] = fmaf(cf0, b0.y, accT[3]);
                accT[0] = fmaf(cf1, a1.x, accT[0]);
                accT[1] = fmaf(cf1, a1.y, accT[1]);
                accT[2] = fmaf(cf1, b1.x, accT[2]);
                accT[3] = fmaf(cf1, b1.y, accT[3]);
                e += 2;
            }
            if (e < end) {
                int2 ed = __ldg(&g_edge[e]);
                uint2 u = __ldg((const uint2*)(zr + (size_t)ed.x * DH + c0));
                float cf = __int_as_float(ed.y);
                float2 p0 = __half22float2(*(__half2*)&u.x);
                float2 p1 = __half22float2(*(__half2*)&u.y);
                accT[0] = fmaf(cf, p0.x, accT[0]);
                accT[1] = fmaf(cf, p0.y, accT[1]);
                accT[2] = fmaf(cf, p1.x, accT[2]);
                accT[3] = fmaf(cf, p1.y, accT[3]);
            }
        }

        *(float4*)(outf + (size_t)w * DH + c0) = make_float4(accT[0], accT[1], accT[2], accT[3]);
        // fused logits: warp holds the full 128-value row across lanes
        float lg[NCLS];
#pragma unroll
        for (int c = 0; c < NCLS; c++) {
            float s = accT[0] * WsL[(c0 + 0) * NCLS + c];
            s = fmaf(accT[1], WsL[(c0 + 1) * NCLS + c], s);
            s = fmaf(accT[2], WsL[(c0 + 2) * NCLS + c], s);
            s = fmaf(accT[3], WsL[(c0 + 3) * NCLS + c], s);
            lg[c] = s;
        }
#pragma unroll
        for (int o = 16; o >= 1; o >>= 1)
#pragma unroll
            for (int c = 0; c < NCLS; c++)
                lg[c] += __shfl_xor_sync(0xffffffffu, lg[c], o);
        if (lane < NCLS)
            logits[(size_t)w * NCLS + lane] = lg[lane] + bsL[lane];
    } else {
        float accT[4];
#pragma unroll
        for (int j = 0; j < 4; j++)
            accT[j] = bias[c0 + j] + bias[DH + c0 + j] + bias[2 * DH + c0 + j];

#pragma unroll
        for (int r = 0; r < RR; r++) {
            int idx = r * NN + w;
            int e = g_off[idx];
            int end = g_off[idx + 1];
            const __half* zr = z + (size_t)r * NN * DH;
            if ((e & 1) && e < end) {
                int2 ed = __ldg(&g_edge[e]);
                uint2 u = __ldg((const uint2*)(zr + (size_t)ed.x * DH + c0));
                float cf = __int_as_float(ed.y);
                float2 p0 = __half22float2(*(__half2*)&u.x);
                float2 p1 = __half22float2(*(__half2*)&u.y);
                accT[0] = fmaf(cf, p0.x, accT[0]);
                accT[1] = fmaf(cf, p0.y, accT[1]);
                accT[2] = fmaf(cf, p1.x, accT[2]);
                accT[3] = fmaf(cf, p1.y, accT[3]);
                e++;
            }
            int npair = (end - e) >> 1;
            if (npair > 0) {
                int4 ed = __ldg((const int4*)(g_edge + e));
                for (int it = 1; it < npair; it++) {
                    uint2 u0 = __ldg((const uint2*)(zr + (size_t)ed.x * DH + c0));
                    uint2 u1 = __ldg((const uint2*)(zr + (size_t)ed.z * DH + c0));
                    int4 nx = __ldg((const int4*)(g_edge + e + 2));
                    float cf0 = __int_as_float(ed.y);
                    float cf1 = __int_as_float(ed.w);
                    float2 a0 = __half22float2(*(__half2*)&u0.x);
                    float2 b0 = __half22float2(*(__half2*)&u0.y);
                    float2 a1 = __half22float2(*(__half2*)&u1.x);
                    float2 b1 = __half22float2(*(__half2*)&u1.y);
                    accT[0] = fmaf(cf0, a0.x, accT[0]);
                    accT[1] = fmaf(cf0, a0.y, accT[1]);
                    accT[2] = fmaf(cf0, b0.x, accT[2]);
                    accT[3] = fmaf(cf0, b0.y, accT[3]);
                    accT[0] = fmaf(cf1, a1.x, accT[0]);
                    accT[1] = fmaf(cf1, a1.y, accT[1]);
                    accT[2] = fmaf(cf1, b1.x, accT[2]);
                    accT[3] = fmaf(cf1, b1.y, accT[3]);
                    ed = nx;
                    e += 2;
                }
                uint2 u0 = __ldg((const uint2*)(zr + (size_t)ed.x * DH + c0));
                uint2 u1 = __ldg((const uint2*)(zr + (size_t)ed.z * DH + c0));
                float cf0 = __int_as_float(ed.y);
                float cf1 = __int_as_float(ed.w);
                float2 a0 = __half22float2(*(__half2*)&u0.x);
                float2 b0 = __half22float2(*(__half2*)&u0.y);
                float2 a1 = __half22float2(*(__half2*)&u1.x);
                float2 b1 = __half22float2(*(__half2*)&u1.y);
                accT[0] = fmaf(cf0, a0.x, accT[0]);
                accT[1] = fmaf(cf0, a0.y, accT[1]);
                accT[2] = fmaf(cf0, b0.x, accT[2]);
                accT[3] = fmaf(cf0, b0.y, accT[3]);
                accT[0] = fmaf(cf1, a1.x, accT[0]);
                accT[1] = fmaf(cf1, a1.y, accT[1]);
                accT[2] = fmaf(cf1, b1.x, accT[2]);
                accT[3] = fmaf(cf1, b1.y, accT[3]);
                e += 2;
            }
            if (e < end) {
                int2 ed = __ldg(&g_edge[e]);
                uint2 u = __ldg((const uint2*)(zr + (size_t)ed.x * DH + c0));
                float cf = __int_as_float(ed.y);
                float2 p0 = __half22float2(*(__half2*)&u.x);
                float2 p1 = __half22float2(*(__half2*)&u.y);
                accT[0] = fmaf(cf, p0.x, accT[0]);
                accT[1] = fmaf(cf, p0.y, accT[1]);
                accT[2] = fmaf(cf, p1.x, accT[2]);
                accT[3] = fmaf(cf, p1.y, accT[3]);
            }
        }

#pragma unroll
        for (int j = 0; j < 4; j++)
            accT[j] = (accT[j] > 0.f) ? accT[j] : NEG_SLOPE * accT[j];
        __half2 h0 = __floats2half2_rn(accT[0], accT[1]);
        __half2 h1 = __floats2half2_rn(accT[2], accT[3]);
        __half2* oh = (__half2*)(outh + (size_t)w * DH + c0);
        oh[0] = h0; oh[1] = h1;
    }
}

// ================= launch =================
extern "C" void kernel_launch(void* const* d_in, const int* in_sizes, int n_in,
                              void* d_out, int out_size) {
    const float* x   = (const float*)d_in[0];
    const int*   src = (const int*)  d_in[1];
    const int*   dst = (const int*)  d_in[2];
    const float* W0  = (const float*)d_in[3];
    const float* b0  = (const float*)d_in[4];
    const float* W1  = (const float*)d_in[5];
    const float* b1  = (const float*)d_in[6];
    const float* fcW = (const float*)d_in[7];
    const float* fcb = (const float*)d_in[8];

    float* out    = (float*)d_out;
    float* h2     = out;
    float* logits = out + (size_t)NN * DH;

    const int T = 256;

    __half* zbuf;  cudaGetSymbolAddress((void**)&zbuf, g_z);
    __half *x16, *h16, *w0p, *w1p;
    cudaGetSymbolAddress((void**)&x16, g_x16);
    cudaGetSymbolAddress((void**)&h16, g_h16);
    cudaGetSymbolAddress((void**)&w0p, g_w0);
    cudaGetSymbolAddress((void**)&w1p, g_w1);

    cudaFuncSetAttribute(mma_gemm, cudaFuncAttributeMaxDynamicSharedMemorySize, GS_TOTAL);

    const int gemmBlocks = (NN + 127) / 128;
    const int gatherGrid = NN / 8;

    // (0..2) conversions, (3) layer-0 GEMM  -> ncu captures launch index 3
    size_t xn4 = (size_t)NN * DIN / 4;
    conv_x_kernel<<<(int)((xn4 + T - 1) / T), T>>>(x, x16, xn4);
    wconv_kernel<<<(RR * DIN * DH + T - 1) / T, T>>>(W0, w0p, DIN);
    wconv_kernel<<<(RR * DH * DH + T - 1) / T, T>>>(W1, w1p, DH);
    mma_gemm<<<dim3(RR, gemmBlocks), T, GS_TOTAL>>>(DIN, x16, w0p, zbuf);

    // degrees + CSR
    deg_zero_kernel<<<(SCAN_N + T - 1) / T, T>>>();
    deg_hist_kernel<<<(RR * EE + T - 1) / T, T>>>(src, dst);
    deg_scale_kernel<<<(SCAN_N + T - 1) / T, T>>>();
    scan1_kernel<<<SCAN_NB, SCAN_B>>>();
    scan2_kernel<<<1, 32>>>();
    scan3_kernel<<<SCAN_NB, SCAN_B>>>();
    fill_kernel<<<(RR * EE + T - 1) / T, T>>>(src, dst);

    // layer 0 gather -> h (fp16)
    gather_kernel<0><<<gatherGrid, T>>>(zbuf, b0, nullptr, h16, nullptr, nullptr, nullptr);

    // layer 1
    mma_gemm<<<dim3(RR, gemmBlocks), T, GS_TOTAL>>>(DH, h16, w1p, zbuf);
    gather_kernel<1><<<gatherGrid, T>>>(zbuf, b1, h2, nullptr, fcW, fcb, logits);
}

// round 14
// speedup vs baseline: 1.4564x; 1.4564x over previous
#include <cuda_runtime.h>
#include <cuda_bf16.h>
#include <cuda_fp16.h>
#include <cstdint>

#define NN 100000
#define EE 600000
#define RR 3
#define DIN 256
#define DH  128
#define NCLS 16
#define NEG_SLOPE 0.01f

#define SCAN_N (RR * NN)
#define SCAN_B 1024
#define SCAN_NB ((SCAN_N + SCAN_B - 1) / SCAN_B)

// GEMM tiling: KC=64, 2 smem tiles per stage (A, B), double buffered
#define KC 64
#define ASTR 72
#define TILE_B (128 * ASTR * 2)     // 18432 B
#define STAGE_B (2 * TILE_B)        // 36864 B
#define GS_TOTAL (2 * STAGE_B)      // 73728 B

__device__ __forceinline__ uint32_t smem_u32(const void* p) {
    uint32_t a;
    asm("{ .reg .u64 t; cvta.to.shared.u64 t, %1; cvt.u32.u64 %0, t; }" : "=r"(a) : "l"(p));
    return a;
}

#define LDSM4(r, a) \
    asm volatile("ldmatrix.sync.aligned.m8n8.x4.shared.b16 {%0,%1,%2,%3}, [%4];" \
        : "=r"((r)[0]), "=r"((r)[1]), "=r"((r)[2]), "=r"((r)[3]) : "r"(a))

__device__ __forceinline__ void mma16816h(float* d, const uint32_t* a, const uint32_t* b) {
    asm volatile("mma.sync.aligned.m16n8k16.row.col.f32.f16.f16.f32 "
                 "{%0,%1,%2,%3}, {%4,%5,%6,%7}, {%8,%9}, {%0,%1,%2,%3};"
                 : "+f"(d[0]), "+f"(d[1]), "+f"(d[2]), "+f"(d[3])
                 : "r"(a[0]), "r"(a[1]), "r"(a[2]), "r"(a[3]), "r"(b[0]), "r"(b[1]));
}

// ================= scratch =================
__device__ __half g_z[(size_t)RR * NN * DH];          // fp16 z: 77 MB (fits L2)
__device__ __half g_x16[(size_t)NN * DIN];
__device__ __half g_h16[(size_t)NN * DH];
__device__ __half g_w0[RR * DH * DIN];                // transposed [r][n][k], fp16
__device__ __half g_w1[RR * DH * DH];
__device__ float g_so[SCAN_N];
__device__ float g_si[SCAN_N];
__device__ int   g_co[SCAN_N];
__device__ int   g_ci[SCAN_N];
__device__ int   g_off[SCAN_N + 1];
__device__ int   g_cursor[SCAN_N];
__device__ int   g_bsum[SCAN_NB];
__device__ int2  g_edge[RR * EE];     // {src, float_bits(so[src]*si[dst])}

// ================= degrees + CSR =================
__global__ void deg_zero_kernel() {
    int i = blockIdx.x * blockDim.x + threadIdx.x;
    if (i < SCAN_N) { g_co[i] = 0; g_ci[i] = 0; }
}
__global__ void deg_hist_kernel(const int* __restrict__ src, const int* __restrict__ dst) {
    int i = blockIdx.x * blockDim.x + threadIdx.x;
    if (i >= RR * EE) return;
    int r = i / EE;
    atomicAdd(&g_co[r * NN + src[i]], 1);
    atomicAdd(&g_ci[r * NN + dst[i]], 1);
}
__global__ void deg_scale_kernel() {
    int i = blockIdx.x * blockDim.x + threadIdx.x;
    if (i >= SCAN_N) return;
    int co = g_co[i]; if (co < 1) co = 1;
    int ci = g_ci[i]; if (ci < 1) ci = 1;
    g_so[i] = rsqrtf((float)co);
    g_si[i] = rsqrtf((float)ci);
}
__global__ void scan1_kernel() {
    __shared__ int tmp[SCAN_B];
    int t = threadIdx.x;
    int i = blockIdx.x * SCAN_B + t;
    int v = (i < SCAN_N) ? g_ci[i] : 0;
    tmp[t] = v;
    __syncthreads();
    for (int o = 1; o < SCAN_B; o <<= 1) {
        int u = (t >= o) ? tmp[t - o] : 0;
        __syncthreads();
        tmp[t] += u;
        __syncthreads();
    }
    if (i < SCAN_N) g_off[i] = tmp[t] - v;
    if (t == SCAN_B - 1) g_bsum[blockIdx.x] = tmp[t];
}
__global__ void scan2_kernel() {
    if (threadIdx.x == 0 && blockIdx.x == 0) {
        int run = 0;
        for (int b = 0; b < SCAN_NB; b++) { int v = g_bsum[b]; g_bsum[b] = run; run += v; }
        g_off[SCAN_N] = run;
    }
}
__global__ void scan3_kernel() {
    int i = blockIdx.x * SCAN_B + threadIdx.x;
    if (i < SCAN_N) {
        int v = g_off[i] + g_bsum[blockIdx.x];
        g_off[i] = v;
        g_cursor[i] = v;
    }
}
__global__ void fill_kernel(const int* __restrict__ src, const int* __restrict__ dst) {
    int i = blockIdx.x * blockDim.x + threadIdx.x;
    if (i >= RR * EE) return;
    int r = i / EE;
    int s = src[i], d = dst[i];
    int pos = atomicAdd(&g_cursor[r * NN + d], 1);
    float coef = g_so[r * NN + s] * g_si[r * NN + d];
    g_edge[pos] = make_int2(s, __float_as_int(coef));
}

// ================= fp16 conversions =================
__global__ void conv_x_kernel(const float* __restrict__ in,
                              __half* __restrict__ o16, size_t n4) {
    size_t i = (size_t)blockIdx.x * blockDim.x + threadIdx.x;
    if (i >= n4) return;
    float4 v = ((const float4*)in)[i];
    __half2 h0 = __floats2half2_rn(v.x, v.y);
    __half2 h1 = __floats2half2_rn(v.z, v.w);
    ((__half2*)o16)[i * 2]     = h0;
    ((__half2*)o16)[i * 2 + 1] = h1;
}

// W [RR, K, DH] -> Wt fp16 [RR, DH(n), K]
__global__ void wconv_kernel(const float* __restrict__ W,
                             __half* __restrict__ t, int K) {
    int i = blockIdx.x * blockDim.x + threadIdx.x;
    if (i >= RR * K * DH) return;
    int r = i / (K * DH);
    int rem = i - r * K * DH;
    int k = rem / DH;
    int n = rem - k * DH;
    t[(size_t)r * DH * K + (size_t)n * K + k] = __float2half_rn(W[i]);
}

// ================= plain fp16 GEMM (KC=64, 2 CTAs/SM) =================
__device__ __forceinline__ void load_stage(uint32_t sb, int st, int c, int K, int mbase,
                                           const __half* __restrict__ A,
                                           const __half* __restrict__ B, int tid) {
    int k0 = c * KC;
    uint32_t sbase = sb + st * STAGE_B;
#pragma unroll
    for (int i = 0; i < 8; i++) {
        int idx = tid + i * 256;          // 2048 = 2 tiles x 1024 segs
        int tile = idx >> 10;
        int p = idx & 1023;
        int row = p >> 3, seg = p & 7;    // 8 segs of 16B per 128B row
        uint32_t sa = sbase + tile * TILE_B + row * (ASTR * 2) + seg * 16;
        const __half* gsrc;
        int sz = 16;
        if (tile == 0) {
            int grow = mbase + row;
            gsrc = A + (size_t)grow * K + k0 + seg * 8;
            if (grow >= NN) sz = 0;
        } else {
            gsrc = B + (size_t)row * K + k0 + seg * 8;
        }
        asm volatile("cp.async.cg.shared.global [%0], [%1], 16, %2;"
                     :: "r"(sa), "l"(gsrc), "r"(sz));
    }
    asm volatile("cp.async.commit_group;" ::: "memory");
}

__global__ __launch_bounds__(256, 2)
void mma_gemm(int K,
              const __half* __restrict__ A,
              const __half* __restrict__ Ball,
              __half* __restrict__ Call) {
    extern __shared__ char smem[];
    uint32_t sb = smem_u32(smem);
    int tid = threadIdx.x, wid = tid >> 5, lane = tid & 31;
    int r = blockIdx.x;                  // fast dim: relation (A shared in L2)
    int mbase = blockIdx.y * 128;
    const __half* B = Ball + (size_t)r * DH * K;
    __half* C = Call + (size_t)r * NN * DH;
    const int warp_m = (wid & 3) * 32;
    const int warp_n = (wid >> 2) * 64;

    float acc[2][8][4];
#pragma unroll
    for (int mt = 0; mt < 2; mt++)
#pragma unroll
        for (int nt = 0; nt < 8; nt++)
#pragma unroll
            for (int q = 0; q < 4; q++) acc[mt][nt][q] = 0.0f;

    const int nchunk = K / KC;
    load_stage(sb, 0, 0, K, mbase, A, B, tid);

    for (int c = 0; c < nchunk; c++) {
        if (c + 1 < nchunk) {
            load_stage(sb, (c + 1) & 1, c + 1, K, mbase, A, B, tid);
            asm volatile("cp.async.wait_group 1;" ::: "memory");
        } else {
            asm volatile("cp.async.wait_group 0;" ::: "memory");
        }
        __syncthreads();

        uint32_t base = sb + (c & 1) * STAGE_B;
#pragma unroll
        for (int ks = 0; ks < KC; ks += 16) {
            uint32_t ah[2][4];
            const int ar = lane & 15;
            const int ac = ks + ((lane >> 4) << 3);
#pragma unroll
            for (int mt = 0; mt < 2; mt++) {
                uint32_t addr = base + ((warp_m + mt * 16 + ar) * ASTR + ac) * 2;
                LDSM4(ah[mt], addr);
            }
            const int br = ((lane >> 4) << 3) + (lane & 7);
            const int bc = ks + (((lane >> 3) & 1) << 3);
#pragma unroll
            for (int j = 0; j < 4; j++) {
                uint32_t b4[4];
                uint32_t addr = base + TILE_B + ((warp_n + j * 16 + br) * ASTR + bc) * 2;
                LDSM4(b4, addr);
#pragma unroll
                for (int mt = 0; mt < 2; mt++) {
#pragma unroll
                    for (int half = 0; half < 2; half++) {
                        mma16816h(acc[mt][j * 2 + half], ah[mt], &b4[half * 2]);
                    }
                }
            }
        }
        __syncthreads();
    }

    // epilogue: fp32 acc -> fp16 z
#pragma unroll
    for (int mt = 0; mt < 2; mt++) {
        int row0 = mbase + warp_m + mt * 16 + (lane >> 2);
#pragma unroll
        for (int nt = 0; nt < 8; nt++) {
            int col = warp_n + nt * 8 + (lane & 3) * 2;
            if (row0 < NN)
                *(__half2*)(C + (size_t)row0 * DH + col) =
                    __floats2half2_rn(acc[mt][nt][0], acc[mt][nt][1]);
            if (row0 + 8 < NN)
                *(__half2*)(C + (size_t)(row0 + 8) * DH + col) =
                    __floats2half2_rn(acc[mt][nt][2], acc[mt][nt][3]);
        }
    }
}

// ================= gather: warp per dst node, fp16 z, unroll x2 (R12 frozen) =================
// MODE 0: leaky -> h fp16.  MODE 1: h2 f32 out.
template <int MODE>
__global__ __launch_bounds__(256)
void gather_kernel(const __half* __restrict__ z, const float* __restrict__ bias,
                   float* __restrict__ outf, __half* __restrict__ outh) {
    int w = blockIdx.x * 8 + (threadIdx.x >> 5);
    if (w >= NN) return;
    int lane = threadIdx.x & 31;
    int c0 = lane * 4;

    float accT[4];
#pragma unroll
    for (int j = 0; j < 4; j++)
        accT[j] = bias[c0 + j] + bias[DH + c0 + j] + bias[2 * DH + c0 + j];

#pragma unroll
    for (int r = 0; r < RR; r++) {
        int idx = r * NN + w;
        int beg = g_off[idx];
        int end = g_off[idx + 1];
        const __half* zr = z + (size_t)r * NN * DH;
        int e = beg;
        for (; e + 2 <= end; e += 2) {
            int2 e0 = __ldg(&g_edge[e]);
            int2 e1 = __ldg(&g_edge[e + 1]);
            uint2 u0 = __ldg((const uint2*)(zr + (size_t)e0.x * DH + c0));
            uint2 u1 = __ldg((const uint2*)(zr + (size_t)e1.x * DH + c0));
            float c0f = __int_as_float(e0.y);
            float c1f = __int_as_float(e1.y);
            float2 a0 = __half22float2(*(__half2*)&u0.x);
            float2 b0 = __half22float2(*(__half2*)&u0.y);
            float2 a1 = __half22float2(*(__half2*)&u1.x);
            float2 b1 = __half22float2(*(__half2*)&u1.y);
            accT[0] = fmaf(c0f, a0.x, accT[0]);
            accT[1] = fmaf(c0f, a0.y, accT[1]);
            accT[2] = fmaf(c0f, b0.x, accT[2]);
            accT[3] = fmaf(c0f, b0.y, accT[3]);
            accT[0] = fmaf(c1f, a1.x, accT[0]);
            accT[1] = fmaf(c1f, a1.y, accT[1]);
            accT[2] = fmaf(c1f, b1.x, accT[2]);
            accT[3] = fmaf(c1f, b1.y, accT[3]);
        }
        if (e < end) {
            int2 e0 = __ldg(&g_edge[e]);
            uint2 u0 = __ldg((const uint2*)(zr + (size_t)e0.x * DH + c0));
            float c0f = __int_as_float(e0.y);
            float2 a0 = __half22float2(*(__half2*)&u0.x);
            float2 b0 = __half22float2(*(__half2*)&u0.y);
            accT[0] = fmaf(c0f, a0.x, accT[0]);
            accT[1] = fmaf(c0f, a0.y, accT[1]);
            accT[2] = fmaf(c0f, b0.x, accT[2]);
            accT[3] = fmaf(c0f, b0.y, accT[3]);
        }
    }

    if (MODE == 0) {
#pragma unroll
        for (int j = 0; j < 4; j++)
            accT[j] = (accT[j] > 0.f) ? accT[j] : NEG_SLOPE * accT[j];
        __half2 h0 = __floats2half2_rn(accT[0], accT[1]);
        __half2 h1 = __floats2half2_rn(accT[2], accT[3]);
        __half2* oh = (__half2*)(outh + (size_t)w * DH + c0);
        oh[0] = h0; oh[1] = h1;
    } else {
        *(float4*)(outf + (size_t)w * DH + c0) = make_float4(accT[0], accT[1], accT[2], accT[3]);
    }
}

// ================= logits =================
__global__ __launch_bounds__(256)
void logits_kernel(const float* __restrict__ h2, const float* __restrict__ fcW,
                   const float* __restrict__ fcb, float* __restrict__ out) {
    __shared__ float Ws[DH * NCLS];
    __shared__ float bs[NCLS];
    int tid = threadIdx.x;
    for (int i = tid; i < DH * NCLS; i += 256) Ws[i] = fcW[i];
    if (tid < NCLS) bs[tid] = fcb[tid];
    __syncthreads();

    int n = blockIdx.x * 256 + tid;
    if (n >= NN) return;
    const float4* row = (const float4*)(h2 + (size_t)n * DH);
    float acc[NCLS];
#pragma unroll
    for (int c = 0; c < NCLS; c++) acc[c] = bs[c];
    for (int k4 = 0; k4 < DH / 4; k4++) {
        float4 hv = row[k4];
        float hs[4] = {hv.x, hv.y, hv.z, hv.w};
#pragma unroll
        for (int u = 0; u < 4; u++) {
            int k = k4 * 4 + u;
#pragma unroll
            for (int c = 0; c < NCLS; c++) acc[c] = fmaf(hs[u], Ws[k * NCLS + c], acc[c]);
        }
    }
    float* o = out + (size_t)n * NCLS;
#pragma unroll
    for (int c = 0; c < NCLS; c++) o[c] = acc[c];
}

// ================= launch =================
extern "C" void kernel_launch(void* const* d_in, const int* in_sizes, int n_in,
                              void* d_out, int out_size) {
    const float* x   = (const float*)d_in[0];
    const int*   src = (const int*)  d_in[1];
    const int*   dst = (const int*)  d_in[2];
    const float* W0  = (const float*)d_in[3];
    const float* b0  = (const float*)d_in[4];
    const float* W1  = (const float*)d_in[5];
    const float* b1  = (const float*)d_in[6];
    const float* fcW = (const float*)d_in[7];
    const float* fcb = (const float*)d_in[8];

    float* out    = (float*)d_out;
    float* h2     = out;
    float* logits = out + (size_t)NN * DH;

    const int T = 256;

    __half* zbuf;  cudaGetSymbolAddress((void**)&zbuf, g_z);
    __half *x16, *h16, *w0p, *w1p;
    cudaGetSymbolAddress((void**)&x16, g_x16);
    cudaGetSymbolAddress((void**)&h16, g_h16);
    cudaGetSymbolAddress((void**)&w0p, g_w0);
    cudaGetSymbolAddress((void**)&w1p, g_w1);

    cudaFuncSetAttribute(mma_gemm, cudaFuncAttributeMaxDynamicSharedMemorySize, GS_TOTAL);

    const int gemmBlocks = (NN + 127) / 128;
    const int gatherGrid = (NN + 7) / 8;

    // (0..2) conversions, (3) layer-0 GEMM  -> ncu captures launch index 3
    size_t xn4 = (size_t)NN * DIN / 4;
    conv_x_kernel<<<(int)((xn4 + T - 1) / T), T>>>(x, x16, xn4);
    wconv_kernel<<<(RR * DIN * DH + T - 1) / T, T>>>(W0, w0p, DIN);
    wconv_kernel<<<(RR * DH * DH + T - 1) / T, T>>>(W1, w1p, DH);
    mma_gemm<<<dim3(RR, gemmBlocks), T, GS_TOTAL>>>(DIN, x16, w0p, zbuf);

    // degrees + CSR
    deg_zero_kernel<<<(SCAN_N + T - 1) / T, T>>>();
    deg_hist_kernel<<<(RR * EE + T - 1) / T, T>>>(src, dst);
    deg_scale_kernel<<<(SCAN_N + T - 1) / T, T>>>();
    scan1_kernel<<<SCAN_NB, SCAN_B>>>();
    scan2_kernel<<<1, 32>>>();
    scan3_kernel<<<SCAN_NB, SCAN_B>>>();
    fill_kernel<<<(RR * EE + T - 1) / T, T>>>(src, dst);

    // layer 0 gather -> h (fp16)
    gather_kernel<0><<<gatherGrid, T>>>(zbuf, b0, nullptr, h16);

    // layer 1
    mma_gemm<<<dim3(RR, gemmBlocks), T, GS_TOTAL>>>(DH, h16, w1p, zbuf);
    gather_kernel<1><<<gatherGrid, T>>>(zbuf, b1, h2, nullptr);

    // fc head
    logits_kernel<<<(NN + T - 1) / T, T>>>(h2, fcW, fcb, logits);
}